// round 1
// baseline (speedup 1.0000x reference)
#include <cuda_runtime.h>

// RoI Align (grid-sample style, AH=AW=14, spatial_scale=1/16)
// features: [N=2, C=512, H=100, W=152] fp32   (d_in[0])
// rois:     [R=512, 5] (b, x1, y1, x2, y2)    (d_in[1])
// out:      [R, C, 14, 14] fp32
//
// Strategy: one block per (roi, channel-chunk). Precompute the 196 bins'
// 4 gather offsets + 4 bilinear weights in shared memory (same for every
// channel), then stream channels with float4 (4-bin) stores.

#define AH 14
#define AW 14
#define NBINS (AH * AW)          // 196
#define NB4   (NBINS / 4)        // 49 float4 groups
#define C_TOT 512
#define FH 100
#define FW 152
#define PLANE (FH * FW)          // 15200
#define SCALE 0.0625f
#define C_CHUNKS 8
#define C_PER (C_TOT / C_CHUNKS) // 64
#define THREADS 256

__global__ __launch_bounds__(THREADS)
void roi_align_kernel(const float* __restrict__ feat,
                      const float* __restrict__ rois,
                      float* __restrict__ out)
{
    __shared__ int4   s_off[NBINS];   // 4 gather offsets per bin
    __shared__ float4 s_w[NBINS];     // 4 bilinear weights per bin
    __shared__ int    s_base;         // batch plane base (b * C*H*W)

    const int r   = blockIdx.x;
    const int tid = threadIdx.x;

    // ---- per-roi setup: 196 threads each compute one bin ----
    if (tid < NBINS) {
        const float bf = rois[r * 5 + 0];
        const float x1 = rois[r * 5 + 1] * SCALE;
        const float y1 = rois[r * 5 + 2] * SCALE;
        const float x2 = rois[r * 5 + 3] * SCALE;
        const float y2 = rois[r * 5 + 4] * SCALE;

        const float roi_w = fmaxf(x2 - x1, 0.0f);
        const float roi_h = fmaxf(y2 - y1, 0.0f);
        const float bin_w = roi_w * (1.0f / (AW - 1));
        const float bin_h = roi_h * (1.0f / (AH - 1));

        const int ybin = tid / AW;
        const int xbin = tid - ybin * AW;

        float ys = y1 + (float)ybin * bin_h;
        float xs = x1 + (float)xbin * bin_w;
        ys = fminf(fmaxf(ys, 0.0f), (float)(FH - 1));
        xs = fminf(fmaxf(xs, 0.0f), (float)(FW - 1));

        const int y0 = (int)floorf(ys);
        const int x0 = (int)floorf(xs);
        const int y1i = min(y0 + 1, FH - 1);
        const int x1i = min(x0 + 1, FW - 1);

        const float wy = ys - (float)y0;
        const float wx = xs - (float)x0;

        int4 o;
        o.x = y0  * FW + x0;
        o.y = y0  * FW + x1i;
        o.z = y1i * FW + x0;
        o.w = y1i * FW + x1i;
        s_off[tid] = o;

        float4 w;
        w.x = (1.0f - wy) * (1.0f - wx);
        w.y = (1.0f - wy) * wx;
        w.z = wy * (1.0f - wx);
        w.w = wy * wx;
        s_w[tid] = w;

        if (tid == 0) s_base = (int)bf * (C_TOT * PLANE);
    }
    __syncthreads();

    // ---- channel sweep: this block handles C_PER channels ----
    const int c0 = blockIdx.y * C_PER;
    const float* __restrict__ fbatch = feat + s_base;
    // output base for this roi (int offsets safe: total out = 51.4M < 2^31)
    const int out_roi = r * (C_TOT * NBINS);

    // flattened work: C_PER channels x NB4 float4-groups
    for (int idx = tid; idx < C_PER * NB4; idx += THREADS) {
        const int c_loc = idx / NB4;
        const int g     = idx - c_loc * NB4;
        const int c     = c0 + c_loc;
        const float* __restrict__ f = fbatch + c * PLANE;
        const int bin = g * 4;

        float4 v;
        {
            const int4   o = s_off[bin + 0];
            const float4 w = s_w[bin + 0];
            v.x = w.x * f[o.x] + w.y * f[o.y] + w.z * f[o.z] + w.w * f[o.w];
        }
        {
            const int4   o = s_off[bin + 1];
            const float4 w = s_w[bin + 1];
            v.y = w.x * f[o.x] + w.y * f[o.y] + w.z * f[o.z] + w.w * f[o.w];
        }
        {
            const int4   o = s_off[bin + 2];
            const float4 w = s_w[bin + 2];
            v.z = w.x * f[o.x] + w.y * f[o.y] + w.z * f[o.z] + w.w * f[o.w];
        }
        {
            const int4   o = s_off[bin + 3];
            const float4 w = s_w[bin + 3];
            v.w = w.x * f[o.x] + w.y * f[o.y] + w.z * f[o.z] + w.w * f[o.w];
        }

        *reinterpret_cast<float4*>(out + out_roi + c * NBINS + bin) = v;
    }
}

extern "C" void kernel_launch(void* const* d_in, const int* in_sizes, int n_in,
                              void* d_out, int out_size)
{
    const float* feat = (const float*)d_in[0];
    const float* rois = (const float*)d_in[1];
    float* out = (float*)d_out;

    const int R = in_sizes[1] / 5;   // 512

    dim3 grid(R, C_CHUNKS, 1);
    dim3 block(THREADS, 1, 1);
    roi_align_kernel<<<grid, block>>>(feat, rois, out);
}

// round 2
// speedup vs baseline: 1.2915x; 1.2915x over previous
#include <cuda_runtime.h>

// RoI Align (AH=AW=14, spatial_scale=1/16), smem-staged patch version.
// features: [2, 512, 100, 152] fp32, rois: [512, 5], out: [512, 512, 14, 14]
//
// One block per (roi, 64-channel chunk). Separable bin coords (14 x + 14 y)
// computed once; per 8-channel group the bounded RoI patch (<=30x30) is
// staged into smem with coalesced loads, then bilinear interp reads smem.

#define AH 14
#define AW 14
#define NBINS (AH * AW)          // 196
#define NB4   (NBINS / 4)        // 49
#define C_TOT 512
#define FH 100
#define FW 152
#define PLANE (FH * FW)
#define SCALE 0.0625f
#define C_CHUNKS 8
#define C_PER (C_TOT / C_CHUNKS) // 64
#define CG 8                     // channels per smem group
#define THREADS 256
#define MAXP 30                  // max patch rows/cols
#define PITCH 31                 // odd pitch to scatter banks

__global__ __launch_bounds__(THREADS)
void roi_align_kernel(const float* __restrict__ feat,
                      const float* __restrict__ rois,
                      float* __restrict__ out)
{
    __shared__ float s_patch[CG][MAXP * PITCH];  // ~29.8 KB
    __shared__ float s_wx[AW], s_wy[AH];
    __shared__ int   s_cx[AW], s_cy[AH];         // patch-relative col/row of corner 0
    __shared__ int   s_cx0, s_cy0, s_wcols, s_hrows, s_base;

    const int r    = blockIdx.x;
    const int tid  = threadIdx.x;
    const int wid  = tid >> 5;
    const int lane = tid & 31;

    // ---- per-roi separable setup (28 threads: 14 for x, 14 for y) ----
    if (tid < 28) {
        const bool isx = tid < 14;
        const int  i   = isx ? tid : tid - 14;
        const float p1  = rois[r * 5 + (isx ? 1 : 2)] * SCALE;
        const float p2  = rois[r * 5 + (isx ? 3 : 4)] * SCALE;
        const float lim = isx ? (float)(FW - 1) : (float)(FH - 1);

        const float len   = fmaxf(p2 - p1, 0.0f);
        const float binsz = len * (1.0f / 13.0f);

        float s = fminf(fmaxf(p1 + (float)i * binsz, 0.0f), lim);
        const int   i0 = (int)floorf(s);
        const float w  = s - (float)i0;

        // bin 0 gives the patch origin (coords are monotone in bin index)
        const float s0 = fminf(fmaxf(p1, 0.0f), lim);
        const int base0 = (int)floorf(s0);

        if (isx) {
            s_wx[i] = w; s_cx[i] = i0 - base0;
            if (i == 13) s_wcols = i0 - base0 + 2;
            if (i == 0)  s_cx0   = base0;
        } else {
            s_wy[i] = w; s_cy[i] = i0 - base0;
            if (i == 13) s_hrows = i0 - base0 + 2;
            if (i == 0)  s_cy0   = base0;
        }
    }
    if (tid == 28) s_base = (int)rois[r * 5] * (C_TOT * PLANE);
    __syncthreads();

    const int wcols = s_wcols;
    const int hrows = s_hrows;
    const int cx0   = s_cx0;
    const int cy0   = s_cy0;
    const int c0    = blockIdx.y * C_PER;
    const float* __restrict__ fbatch = feat + s_base;
    const int out_roi = r * (C_TOT * NBINS);

    for (int cg = 0; cg < C_PER / CG; cg++) {
        const int cbase = c0 + cg * CG;

        // ---- stage CG channel patches (coalesced row segments) ----
        #pragma unroll
        for (int ch = 0; ch < CG; ch++) {
            const float* __restrict__ fp = fbatch + (cbase + ch) * PLANE;
            for (int ry = wid; ry < hrows; ry += (THREADS / 32)) {
                const int gy = min(cy0 + ry, FH - 1);
                if (lane < wcols)
                    s_patch[ch][ry * PITCH + lane] = fp[gy * FW + min(cx0 + lane, FW - 1)];
            }
        }
        __syncthreads();

        // ---- compute: CG channels x 49 float4 groups ----
        for (int widx = tid; widx < CG * NB4; widx += THREADS) {
            const int ch   = widx / NB4;
            const int g    = widx - ch * NB4;
            const int bin0 = g * 4;
            const float* __restrict__ p = s_patch[ch];

            float v[4];
            #pragma unroll
            for (int k = 0; k < 4; k++) {
                const int bin  = bin0 + k;
                const int ybin = bin / AW;          // const divisor -> mul/shift
                const int xbin = bin - ybin * AW;
                const int row  = s_cy[ybin];
                const int col  = s_cx[xbin];
                const float wy = s_wy[ybin];
                const float wx = s_wx[xbin];

                const int o = row * PITCH + col;
                const float t0 = p[o];
                const float t1 = p[o + 1];
                const float b0 = p[o + PITCH];
                const float b1 = p[o + PITCH + 1];

                const float top = t0 + wx * (t1 - t0);
                const float bot = b0 + wx * (b1 - b0);
                v[k] = top + wy * (bot - top);
            }

            float4 vv = make_float4(v[0], v[1], v[2], v[3]);
            *reinterpret_cast<float4*>(out + out_roi + (cbase + ch) * NBINS + bin0) = vv;
        }
        __syncthreads();
    }
}

extern "C" void kernel_launch(void* const* d_in, const int* in_sizes, int n_in,
                              void* d_out, int out_size)
{
    const float* feat = (const float*)d_in[0];
    const float* rois = (const float*)d_in[1];
    float* out = (float*)d_out;

    const int R = in_sizes[1] / 5;   // 512

    dim3 grid(R, C_CHUNKS, 1);
    dim3 block(THREADS, 1, 1);
    roi_align_kernel<<<grid, block>>>(feat, rois, out);
}

// round 3
// speedup vs baseline: 2.7367x; 2.1190x over previous
#include <cuda_runtime.h>

// RoI Align (AH=AW=14, spatial_scale=1/16).
// features: [2, 512, 100, 152] fp32, rois: [512, 5], out: [512, 512, 14, 14]
//
// Block = (roi, 64-channel chunk). Thread = bin (196 active of 224), bin
// coords/weights in registers. Patch staged channel-vectorized (float4 = 4
// channels per pixel) into a double-buffered smem tile; 16 groups of 4
// channels per block with LDG->reg / compute / STS software pipeline.

#define AH 14
#define AW 14
#define NBINS (AH * AW)          // 196
#define C_TOT 512
#define FH 100
#define FW 152
#define PLANE (FH * FW)
#define SCALE 0.0625f
#define C_CHUNKS 8
#define C_PER (C_TOT / C_CHUNKS) // 64
#define NGRP (C_PER / 4)         // 16 groups of 4 channels
#define TH 224
#define MAXP 30
#define PITCH 30
#define MAXPIX (MAXP * PITCH)    // 900
#define MAXIT 5                  // ceil(900/224)

__global__ __launch_bounds__(TH)
void roi_align_kernel(const float* __restrict__ feat,
                      const float* __restrict__ rois,
                      float* __restrict__ out)
{
    __shared__ float4 s_patch[2][MAXPIX];        // 2 x 14.4 KB
    __shared__ int s_cx0, s_cy0, s_wcols, s_hrows;

    const int r   = blockIdx.x;
    const int tid = threadIdx.x;

    // roi params (broadcast loads)
    const float bf = __ldg(&rois[r * 5 + 0]);
    const float x1 = __ldg(&rois[r * 5 + 1]) * SCALE;
    const float y1 = __ldg(&rois[r * 5 + 2]) * SCALE;
    const float x2 = __ldg(&rois[r * 5 + 3]) * SCALE;
    const float y2 = __ldg(&rois[r * 5 + 4]) * SCALE;

    const float binw = fmaxf(x2 - x1, 0.0f) * (1.0f / 13.0f);
    const float binh = fmaxf(y2 - y1, 0.0f) * (1.0f / 13.0f);

    if (tid == 0) {
        const float sx0  = fminf(fmaxf(x1, 0.0f), (float)(FW - 1));
        const float sx13 = fminf(fmaxf(x1 + 13.0f * binw, 0.0f), (float)(FW - 1));
        const float sy0  = fminf(fmaxf(y1, 0.0f), (float)(FH - 1));
        const float sy13 = fminf(fmaxf(y1 + 13.0f * binh, 0.0f), (float)(FH - 1));
        const int cx0 = (int)floorf(sx0);
        const int cy0 = (int)floorf(sy0);
        s_cx0 = cx0;
        s_cy0 = cy0;
        s_wcols = (int)floorf(sx13) - cx0 + 2;   // <= 30
        s_hrows = (int)floorf(sy13) - cy0 + 2;   // <= 30
    }
    __syncthreads();

    const int cx0   = s_cx0;
    const int cy0   = s_cy0;
    const int wcols = s_wcols;
    const int npix  = s_hrows * wcols;

    const int c0 = blockIdx.y * C_PER;
    const float* __restrict__ fbase = feat + (int)bf * (C_TOT * PLANE) + c0 * PLANE;
    float* __restrict__ obase = out + r * (C_TOT * NBINS) + c0 * NBINS + tid;

    // ---- per-thread bin coords (registers, fixed for whole kernel) ----
    int   o_idx = 0;
    float wx = 0.0f, wy = 0.0f;
    if (tid < NBINS) {
        const int ybin = tid / AW;
        const int xbin = tid - ybin * AW;
        const float xs = fminf(fmaxf(x1 + (float)xbin * binw, 0.0f), (float)(FW - 1));
        const float ys = fminf(fmaxf(y1 + (float)ybin * binh, 0.0f), (float)(FH - 1));
        const int x0 = (int)floorf(xs);
        const int y0 = (int)floorf(ys);
        wx = xs - (float)x0;
        wy = ys - (float)y0;
        o_idx = (y0 - cy0) * PITCH + (x0 - cx0);
    }

    // staging registers
    float4 v0, v1, v2, v3, v4;
    int    p0 = -1, p1 = -1, p2 = -1, p3 = -1, p4 = -1;

    // macro-ish lambdas for the pipeline stages
    auto load_grp = [&](int g) {
        const float* __restrict__ fg = fbase + g * 4 * PLANE;
        p0 = p1 = p2 = p3 = p4 = -1;
        #pragma unroll
        for (int j = 0; j < MAXIT; j++) {
            const int i = tid + j * TH;
            if (i < npix) {
                const int ry = i / wcols;
                const int rx = i - ry * wcols;
                const int gy = min(cy0 + ry, FH - 1);
                const int gx = min(cx0 + rx, FW - 1);
                const int off = gy * FW + gx;
                float4 v;
                v.x = __ldg(fg + off);
                v.y = __ldg(fg + off + PLANE);
                v.z = __ldg(fg + off + 2 * PLANE);
                v.w = __ldg(fg + off + 3 * PLANE);
                const int pi = ry * PITCH + rx;
                if (j == 0) { v0 = v; p0 = pi; }
                if (j == 1) { v1 = v; p1 = pi; }
                if (j == 2) { v2 = v; p2 = pi; }
                if (j == 3) { v3 = v; p3 = pi; }
                if (j == 4) { v4 = v; p4 = pi; }
            }
        }
    };
    auto store_grp = [&](int buf) {
        if (p0 >= 0) s_patch[buf][p0] = v0;
        if (p1 >= 0) s_patch[buf][p1] = v1;
        if (p2 >= 0) s_patch[buf][p2] = v2;
        if (p3 >= 0) s_patch[buf][p3] = v3;
        if (p4 >= 0) s_patch[buf][p4] = v4;
    };

    // prologue: stage group 0
    load_grp(0);
    store_grp(0);
    __syncthreads();

    #pragma unroll 1
    for (int g = 0; g < NGRP; g++) {
        const int buf = g & 1;
        if (g + 1 < NGRP) load_grp(g + 1);   // LDGs in flight over compute

        if (tid < NBINS) {
            const float4* __restrict__ p = s_patch[buf];
            const float4 t0 = p[o_idx];
            const float4 t1 = p[o_idx + 1];
            const float4 b0 = p[o_idx + PITCH];
            const float4 b1 = p[o_idx + PITCH + 1];

            float4 top, bot, vv;
            top.x = fmaf(wx, t1.x - t0.x, t0.x);
            top.y = fmaf(wx, t1.y - t0.y, t0.y);
            top.z = fmaf(wx, t1.z - t0.z, t0.z);
            top.w = fmaf(wx, t1.w - t0.w, t0.w);
            bot.x = fmaf(wx, b1.x - b0.x, b0.x);
            bot.y = fmaf(wx, b1.y - b0.y, b0.y);
            bot.z = fmaf(wx, b1.z - b0.z, b0.z);
            bot.w = fmaf(wx, b1.w - b0.w, b0.w);
            vv.x = fmaf(wy, bot.x - top.x, top.x);
            vv.y = fmaf(wy, bot.y - top.y, top.y);
            vv.z = fmaf(wy, bot.z - top.z, top.z);
            vv.w = fmaf(wy, bot.w - top.w, top.w);

            float* __restrict__ ob = obase + g * 4 * NBINS;
            ob[0]         = vv.x;
            ob[NBINS]     = vv.y;
            ob[2 * NBINS] = vv.z;
            ob[3 * NBINS] = vv.w;
        }

        if (g + 1 < NGRP) store_grp(buf ^ 1);
        __syncthreads();
    }
}

extern "C" void kernel_launch(void* const* d_in, const int* in_sizes, int n_in,
                              void* d_out, int out_size)
{
    const float* feat = (const float*)d_in[0];
    const float* rois = (const float*)d_in[1];
    float* out = (float*)d_out;

    const int R = in_sizes[1] / 5;   // 512

    dim3 grid(R, C_CHUNKS, 1);
    dim3 block(TH, 1, 1);
    roi_align_kernel<<<grid, block>>>(feat, rois, out);
}